// round 7
// baseline (speedup 1.0000x reference)
#include <cuda_runtime.h>
#include <cuda_bf16.h>
#include <cstdint>

// ============================================================================
// GNN_EBM Langevin sampler, collapsed analytic form + packed f32x2 FMA GEMMs,
// full-block (512-thread) GEMM phases for latency coverage.
//
// Identity: with s_i = 1 + rowsum(A)_i/66 > 0, q_i = s_i + (A s)_i/66 > 0:
//   h2[:,i] = q_i * relu(h0),  h0 = x@W_in[:64] + z@W_in[64:66] + b_in
//   E = relu(q64 r@WT1 + bT1)@WT2 + relu(q65 r@WY1 + bY1)@WY2 + const
// grad_z E = Wz^T ( 1[h0>0] .* ( Wfold @ (1[a>0] .* vcat) ) )
//
// RNG: JAX partitionable threefry (split foldlike; bits = o0^o1),
// uniform [-0.99999994,1) -> sqrt(2)*erfinv (XLA Giles poly).
// ============================================================================

#define MT       32
#define NTHREADS 512
#define NSTEPS   20
#define NBLOCKS  (8192 / MT)
#define WSTRIDE  258   // bf16 elements per W row (padded)

__device__ float g_q[2];
__device__ uint2 g_sub[NSTEPS];

// ---------------------------------------------------------------------------
// packed f32x2 helpers
// ---------------------------------------------------------------------------
__device__ __forceinline__ void ffma2(uint64_t& d, uint64_t a, uint64_t b) {
    asm("fma.rn.f32x2 %0, %1, %2, %0;" : "+l"(d) : "l"(a), "l"(b));
}
__device__ __forceinline__ uint64_t pack2(float lo, float hi) {
    uint64_t r;
    asm("mov.b64 %0, {%1, %2};" : "=l"(r) : "f"(lo), "f"(hi));
    return r;
}
__device__ __forceinline__ void unpack2(uint64_t v, float& lo, float& hi) {
    asm("mov.b64 {%0, %1}, %2;" : "=f"(lo), "=f"(hi) : "l"(v));
}
__device__ __forceinline__ float bf16lo(uint32_t w) { return __uint_as_float(w << 16); }
__device__ __forceinline__ float bf16hi(uint32_t w) { return __uint_as_float(w & 0xffff0000u); }
__device__ __forceinline__ uint64_t dup2(float v) { return pack2(v, v); }

// ---------------------------------------------------------------------------
// threefry2x32 — 20 rounds, 5 key injections
// ---------------------------------------------------------------------------
__device__ __forceinline__ uint32_t rotl32(uint32_t v, int r) {
    return (v << r) | (v >> (32 - r));
}

__device__ __forceinline__ void threefry2x32(uint32_t k0, uint32_t k1,
                                             uint32_t x0, uint32_t x1,
                                             uint32_t& o0, uint32_t& o1) {
    uint32_t k2 = k0 ^ k1 ^ 0x1BD11BDAu;
    x0 += k0; x1 += k1;
#define TFR(r) { x0 += x1; x1 = rotl32(x1, (r)); x1 ^= x0; }
    TFR(13) TFR(15) TFR(26) TFR(6)
    x0 += k1; x1 += k2 + 1u;
    TFR(17) TFR(29) TFR(16) TFR(24)
    x0 += k2; x1 += k0 + 2u;
    TFR(13) TFR(15) TFR(26) TFR(6)
    x0 += k0; x1 += k1 + 3u;
    TFR(17) TFR(29) TFR(16) TFR(24)
    x0 += k1; x1 += k2 + 4u;
    TFR(13) TFR(15) TFR(26) TFR(6)
    x0 += k2; x1 += k0 + 5u;
#undef TFR
    o0 = x0; o1 = x1;
}

// XLA f32 ErfInv (Giles polynomial)
__device__ __forceinline__ float jax_erfinv(float x) {
    float w = -log1pf(-x * x);
    float p;
    if (w < 5.0f) {
        w = w - 2.5f;
        p = 2.81022636e-08f;
        p = fmaf(p, w, 3.43273939e-07f);
        p = fmaf(p, w, -3.5233877e-06f);
        p = fmaf(p, w, -4.39150654e-06f);
        p = fmaf(p, w, 0.00021858087f);
        p = fmaf(p, w, -0.00125372503f);
        p = fmaf(p, w, -0.00417768164f);
        p = fmaf(p, w, 0.246640727f);
        p = fmaf(p, w, 1.50140941f);
    } else {
        w = sqrtf(w) - 3.0f;
        p = -0.000200214257f;
        p = fmaf(p, w, 0.000100950558f);
        p = fmaf(p, w, 0.00134934322f);
        p = fmaf(p, w, -0.00367342844f);
        p = fmaf(p, w, 0.00573950773f);
        p = fmaf(p, w, -0.0076224613f);
        p = fmaf(p, w, 0.00943887047f);
        p = fmaf(p, w, 1.00167406f);
        p = fmaf(p, w, 2.83297682f);
    }
    return p * x;
}

__device__ __forceinline__ float jax_normal_from_bits(uint32_t bits) {
    float f = __uint_as_float((bits >> 9) | 0x3f800000u) - 1.0f;
    const float lo = -0.99999994f;
    float u = fmaxf(lo, fmaf(f, 2.0f, lo));
    return 1.41421356237f * jax_erfinv(u);
}

// ---------------------------------------------------------------------------
// prep: q scalars + 20 subkeys
// ---------------------------------------------------------------------------
__device__ __forceinline__ float sigm(float v) { return 1.0f / (1.0f + expf(-v)); }

__global__ void prep_kernel(const float* __restrict__ B) {
    __shared__ float sS[66];
    int t = threadIdx.x;

    if (t < 66) {
        float rs = 0.0f;
        for (int k = 0; k < 66; k++) {
            if (k == t) continue;
            if (t == 65 && k < 64) continue;
            rs += sigm(B[t * 66 + k]);
        }
        sS[t] = 1.0f + rs / 66.0f;
    }
    if (t < 20) {
        uint32_t o0, o1;
        threefry2x32(0u, 42u, 0u, (uint32_t)t, o0, o1);
        g_sub[t] = make_uint2(o0, o1);
    }
    __syncthreads();
    if (t == 0) {
        float acc64 = 0.0f;
        for (int j = 0; j < 66; j++)
            if (j != 64) acc64 += sigm(B[64 * 66 + j]) * sS[j];
        float acc65 = sigm(B[65 * 66 + 64]) * sS[64];
        g_q[0] = sS[64] + acc64 / 66.0f;
        g_q[1] = sS[65] + acc65 / 66.0f;
    }
}

// ---------------------------------------------------------------------------
// main persistent kernel
// ---------------------------------------------------------------------------
struct Smem {
    __nv_bfloat16 W[128][WSTRIDE]; // k<128 -> q0*WT1 ; k>=128 -> q1*WY1
    float C[128][36];              // x-part of h0 (+b_in), [d][m]
    float R[128][36];              // relu(h0), [d][m]
    float M[256][36];              // 1[a>0]*vcat, [k][m]  (also prologue scratch)
    float G0[128][36];             // backward partials (k-half 0)
    float G1[128][36];             // backward partials (k-half 1)
    float Wz[2][128];
    float bcat[256];
    float vcat[256];
    float Z[MT][2];
    float Xs[MT][65];
};

__global__ void __launch_bounds__(NTHREADS, 1)
main_kernel(const float* __restrict__ x, const float* __restrict__ tvec,
            const float* __restrict__ Win, const float* __restrict__ bin,
            const float* __restrict__ WT1, const float* __restrict__ bT1,
            const float* __restrict__ WT2,
            const float* __restrict__ WY1, const float* __restrict__ bY1,
            const float* __restrict__ WY2,
            float* __restrict__ out) {
    extern __shared__ unsigned char sraw[];
    Smem& S = *reinterpret_cast<Smem*>(sraw);
    const int tid = threadIdx.x;
    const int b0 = blockIdx.x * MT;
    const float q0 = g_q[0];
    const float q1 = g_q[1];

    // ---- prologue: stage weights ----
    for (int i = tid; i < 128 * 128; i += NTHREADS) {
        int d = i >> 7, k = i & 127;
        S.W[d][k]       = __float2bfloat16(q0 * WT1[i]);
        S.W[d][k + 128] = __float2bfloat16(q1 * WY1[i]);
    }
    float* WinS = &S.M[0][0];                   // scratch: 64x128 f32 = 32KB
    for (int i = tid; i < 64 * 128; i += NTHREADS) WinS[i] = Win[i];
    for (int i = tid; i < MT * 64; i += NTHREADS) {
        int m = i >> 6, e = i & 63;
        S.Xs[m][e] = x[(size_t)(b0 + m) * 64 + e];
    }
    if (tid < 256) {
        S.bcat[tid] = (tid < 128) ? bT1[tid] : bY1[tid - 128];
        S.vcat[tid] = (tid < 128) ? WT2[tid] : WY2[tid - 128];
    }
    if (tid < 128) {
        S.Wz[0][tid] = Win[64 * 128 + tid];
        S.Wz[1][tid] = Win[65 * 128 + tid];
    }
    if (tid < MT) {
        S.Z[tid][0] = tvec[b0 + tid];
        S.Z[tid][1] = 0.0f;
    }
    __syncthreads();

    // ---- C[d][m] = b_in[d] + sum_e Xs[m][e] * Win[e][d] ----
    {
        int d = tid & 127, m0 = (tid >> 7) << 3;
        float acc[8];
        float bv = bin[d];
        #pragma unroll
        for (int i = 0; i < 8; i++) acc[i] = bv;
        for (int e = 0; e < 64; e++) {
            float w = WinS[(e << 7) + d];
            #pragma unroll
            for (int i = 0; i < 8; i++) acc[i] = fmaf(S.Xs[m0 + i][e], w, acc[i]);
        }
        #pragma unroll
        for (int i = 0; i < 8; i++) S.C[d][m0 + i] = acc[i];
    }
    __syncthreads();

    // ---- Langevin steps ----
    for (int s = 0; s < NSTEPS; s++) {
        // Phase A: R = relu(C + z0*Wz0 + z1*Wz1)
        {
            int d = tid >> 2, m0 = (tid & 3) << 3;
            float wz0 = S.Wz[0][d], wz1 = S.Wz[1][d];
            #pragma unroll
            for (int i = 0; i < 8; i++) {
                int m = m0 + i;
                float h = fmaf(S.Z[m][1], wz1, fmaf(S.Z[m][0], wz0, S.C[d][m]));
                S.R[d][m] = fmaxf(h, 0.0f);
            }
        }
        __syncthreads();

        // Phase B (512 thr): a[m][k] = bcat[k] + sum_d R[d][m]*W[d][k]
        //                    M[k][m] = 1[a>0]*vcat[k]     (FFMA2, m-paired)
        {
            int kg = tid & 127, mg = tid >> 7;
            int k0 = kg << 1, m0 = mg << 3;
            uint64_t acc[2][4];                 // [kj][mpair]
            #pragma unroll
            for (int j = 0; j < 2; j++) {
                uint64_t bv = dup2(S.bcat[k0 + j]);
                #pragma unroll
                for (int p = 0; p < 4; p++) acc[j][p] = bv;
            }
            #pragma unroll 4
            for (int d = 0; d < 128; d++) {
                ulonglong2 ra = *reinterpret_cast<const ulonglong2*>(&S.R[d][m0]);
                ulonglong2 rb = *reinterpret_cast<const ulonglong2*>(&S.R[d][m0 + 4]);
                uint32_t w01 = *reinterpret_cast<const uint32_t*>(&S.W[d][k0]);
                uint64_t w0 = dup2(bf16lo(w01));
                uint64_t w1 = dup2(bf16hi(w01));
                ffma2(acc[0][0], ra.x, w0); ffma2(acc[0][1], ra.y, w0);
                ffma2(acc[0][2], rb.x, w0); ffma2(acc[0][3], rb.y, w0);
                ffma2(acc[1][0], ra.x, w1); ffma2(acc[1][1], ra.y, w1);
                ffma2(acc[1][2], rb.x, w1); ffma2(acc[1][3], rb.y, w1);
            }
            #pragma unroll
            for (int j = 0; j < 2; j++) {
                float v = S.vcat[k0 + j];
                #pragma unroll
                for (int p = 0; p < 4; p++) {
                    float lo, hi;
                    unpack2(acc[j][p], lo, hi);
                    float slo = lo > 0.0f ? v : 0.0f;
                    float shi = hi > 0.0f ? v : 0.0f;
                    *reinterpret_cast<uint64_t*>(&S.M[k0 + j][m0 + 2 * p]) = pack2(slo, shi);
                }
            }
        }
        __syncthreads();

        // Phase C (512 thr): G_h[d][m] = sum_{k in half h} W[d][k]*M[k][m]
        {
            int half = tid >> 8;
            int idx = tid & 255;
            int d0 = (idx >> 2) << 1;           // 64 d-groups of 2
            int m0 = (idx & 3) << 3;            // 4 m-groups of 8
            int kb = half << 7;
            uint64_t acc[2][4];                 // [di][mpair]
            #pragma unroll
            for (int i = 0; i < 2; i++)
                #pragma unroll
                for (int p = 0; p < 4; p++) acc[i][p] = 0ull;
            #pragma unroll 4
            for (int kk = 0; kk < 128; kk += 2) {
                int k = kb + kk;
                ulonglong2 ma  = *reinterpret_cast<const ulonglong2*>(&S.M[k][m0]);
                ulonglong2 ma2 = *reinterpret_cast<const ulonglong2*>(&S.M[k][m0 + 4]);
                ulonglong2 mb  = *reinterpret_cast<const ulonglong2*>(&S.M[k + 1][m0]);
                ulonglong2 mb2 = *reinterpret_cast<const ulonglong2*>(&S.M[k + 1][m0 + 4]);
                #pragma unroll
                for (int di = 0; di < 2; di++) {
                    uint32_t w = *reinterpret_cast<const uint32_t*>(&S.W[d0 + di][k]);
                    uint64_t wl = dup2(bf16lo(w));
                    uint64_t wh = dup2(bf16hi(w));
                    ffma2(acc[di][0], ma.x,  wl); ffma2(acc[di][0], mb.x,  wh);
                    ffma2(acc[di][1], ma.y,  wl); ffma2(acc[di][1], mb.y,  wh);
                    ffma2(acc[di][2], ma2.x, wl); ffma2(acc[di][2], mb2.x, wh);
                    ffma2(acc[di][3], ma2.y, wl); ffma2(acc[di][3], mb2.y, wh);
                }
            }
            float (*G)[36] = half ? S.G1 : S.G0;
            #pragma unroll
            for (int di = 0; di < 2; di++)
                #pragma unroll
                for (int p = 0; p < 4; p++)
                    *reinterpret_cast<uint64_t*>(&G[d0 + di][m0 + 2 * p]) = acc[di][p];
        }
        __syncthreads();

        // Phase D: gz[m][c] = sum_d Wz[c][d]*1[R>0]*(G0+G1); z update + noise
        {
            int g = tid >> 3, j = tid & 7;
            int m = g >> 1, c = g & 1;
            float acc = 0.0f;
            #pragma unroll
            for (int t2 = 0; t2 < 16; t2++) {
                int d = (j << 4) + t2;
                float r = S.R[d][m];
                float gg = S.G0[d][m] + S.G1[d][m];
                acc += (r > 0.0f) ? S.Wz[c][d] * gg : 0.0f;
            }
            acc += __shfl_xor_sync(0xffffffffu, acc, 1);
            acc += __shfl_xor_sync(0xffffffffu, acc, 2);
            acc += __shfl_xor_sync(0xffffffffu, acc, 4);
            if (j == 0) {
                uint2 sk = g_sub[s];
                uint32_t idx = (uint32_t)(2 * (b0 + m) + c);
                uint32_t b1, b2;
                threefry2x32(sk.x, sk.y, 0u, idx, b1, b2);
                float noise = jax_normal_from_bits(b1 ^ b2);
                S.Z[m][c] = S.Z[m][c] - 0.005f * acc + 0.1f * noise;
            }
        }
        __syncthreads();
    }

    if (tid < MT) out[b0 + tid] = S.Z[tid][1];
}

// ---------------------------------------------------------------------------
extern "C" void kernel_launch(void* const* d_in, const int* in_sizes, int n_in,
                              void* d_out, int out_size) {
    (void)in_sizes; (void)n_in; (void)out_size;
    const float* x    = (const float*)d_in[0];
    const float* tv   = (const float*)d_in[1];
    const float* B    = (const float*)d_in[2];
    const float* Win  = (const float*)d_in[3];
    const float* bin  = (const float*)d_in[4];
    const float* WT1  = (const float*)d_in[5];
    const float* bT1  = (const float*)d_in[6];
    const float* WT2  = (const float*)d_in[7];
    const float* WY1  = (const float*)d_in[9];
    const float* bY1  = (const float*)d_in[10];
    const float* WY2  = (const float*)d_in[11];
    float* out = (float*)d_out;

    cudaFuncSetAttribute(main_kernel, cudaFuncAttributeMaxDynamicSharedMemorySize,
                         (int)sizeof(Smem));
    prep_kernel<<<1, 128>>>(B);
    main_kernel<<<NBLOCKS, NTHREADS, sizeof(Smem)>>>(x, tv, Win, bin, WT1, bT1, WT2,
                                                     WY1, bY1, WY2, out);
}

// round 9
// speedup vs baseline: 4.4659x; 4.4659x over previous
#include <cuda_runtime.h>
#include <cuda_bf16.h>
#include <cstdint>

// ============================================================================
// GNN_EBM Langevin sampler — collapsed analytic form, HMMA (mma.sync bf16).
// GEMM1: D1[m,kf] = R[m,d] @ Wf[d,kf]   (m16n8k16 frags, f32 acc)
// GEMM2: D2[m,d]  = Mmask[m,kf] @ Wf[d,kf]^T(kf-major B)
// D1 frag -> A2 frag conversion happens in registers (same thread mapping).
// RNG: JAX partitionable threefry, bit-exact.
// ============================================================================

#define NSTEPS  20
#define MPC     128
#define NTH     512
#define NBLOCKS (8192 / MPC)

#define OFF_BF1 0u          // B frags GEMM1: [kt8][nt32][lane32][2] u32 = 64KB
#define OFF_BF2 65536u      // B frags GEMM2: [kt16][nt16][lane32][2] u32 = 64KB
#define OFF_AF2 131072u     // A frags GEMM2: [mt8][kt16][lane32][4] u32 = 64KB
#define OFF_AF1 196608u     // A frags GEMM1: [mt8][kt8][lane32][4] u32 = 32KB
#define OFF_WZ  229376u     // float2 Wz[128] (1KB)
#define OFF_ZS  230400u     // float2 Z[128]  (1KB)
#define OFF_BV  231424u     // bf16x2 (bcat,vcat)[256] (1KB)
#define SMEM_TOTAL 232448   // = 227KB exactly

__device__ float g_q[2];
__device__ uint2 g_sub[NSTEPS];
__device__ uint32_t gBf1[32768];
__device__ uint32_t gBf2[32768];
__device__ uint32_t gBV[256];

__device__ __forceinline__ uint32_t af1_off(int mt, int kt, int lane) {
    return OFF_AF1 + (uint32_t)((((mt << 3) + kt) << 9) + (lane << 4));
}
__device__ __forceinline__ uint32_t af2_off(int mt, int kt, int lane) {
    return OFF_AF2 + (uint32_t)((((mt << 4) + kt) << 9) + (lane << 4));
}
__device__ __forceinline__ uint32_t bf1_off(int kt, int nt, int lane) {
    return OFF_BF1 + (uint32_t)((((kt << 5) + nt) << 8) + (lane << 3));
}
__device__ __forceinline__ uint32_t bf2_off(int kt, int nt, int lane) {
    return OFF_BF2 + (uint32_t)((((kt << 4) + nt) << 8) + (lane << 3));
}

__device__ __forceinline__ uint32_t cvt_bf16x2(float hi, float lo) {
    uint32_t u;
    asm("cvt.rn.bf16x2.f32 %0, %1, %2;" : "=r"(u) : "f"(hi), "f"(lo));
    return u;
}
__device__ __forceinline__ float bf16lo(uint32_t w) { return __uint_as_float(w << 16); }
__device__ __forceinline__ float bf16hi(uint32_t w) { return __uint_as_float(w & 0xffff0000u); }

#define MMA4(c, a, b0, b1) asm volatile( \
    "mma.sync.aligned.m16n8k16.row.col.f32.bf16.bf16.f32 " \
    "{%0,%1,%2,%3},{%4,%5,%6,%7},{%8,%9},{%0,%1,%2,%3};" \
    : "+f"((c)[0]), "+f"((c)[1]), "+f"((c)[2]), "+f"((c)[3]) \
    : "r"((a)[0]), "r"((a)[1]), "r"((a)[2]), "r"((a)[3]), "r"(b0), "r"(b1))

// --------------------------- threefry / normal -----------------------------
__device__ __forceinline__ uint32_t rotl32(uint32_t v, int r) { return (v << r) | (v >> (32 - r)); }
__device__ __forceinline__ void threefry2x32(uint32_t k0, uint32_t k1, uint32_t x0, uint32_t x1,
                                             uint32_t& o0, uint32_t& o1) {
    uint32_t k2 = k0 ^ k1 ^ 0x1BD11BDAu;
    x0 += k0; x1 += k1;
#define TFR(r) { x0 += x1; x1 = rotl32(x1, (r)); x1 ^= x0; }
    TFR(13) TFR(15) TFR(26) TFR(6)  x0 += k1; x1 += k2 + 1u;
    TFR(17) TFR(29) TFR(16) TFR(24) x0 += k2; x1 += k0 + 2u;
    TFR(13) TFR(15) TFR(26) TFR(6)  x0 += k0; x1 += k1 + 3u;
    TFR(17) TFR(29) TFR(16) TFR(24) x0 += k1; x1 += k2 + 4u;
    TFR(13) TFR(15) TFR(26) TFR(6)  x0 += k2; x1 += k0 + 5u;
#undef TFR
    o0 = x0; o1 = x1;
}
__device__ __forceinline__ float jax_erfinv(float x) {
    float w = -log1pf(-x * x);
    float p;
    if (w < 5.0f) {
        w = w - 2.5f;
        p = 2.81022636e-08f;
        p = fmaf(p, w, 3.43273939e-07f);
        p = fmaf(p, w, -3.5233877e-06f);
        p = fmaf(p, w, -4.39150654e-06f);
        p = fmaf(p, w, 0.00021858087f);
        p = fmaf(p, w, -0.00125372503f);
        p = fmaf(p, w, -0.00417768164f);
        p = fmaf(p, w, 0.246640727f);
        p = fmaf(p, w, 1.50140941f);
    } else {
        w = sqrtf(w) - 3.0f;
        p = -0.000200214257f;
        p = fmaf(p, w, 0.000100950558f);
        p = fmaf(p, w, 0.00134934322f);
        p = fmaf(p, w, -0.00367342844f);
        p = fmaf(p, w, 0.00573950773f);
        p = fmaf(p, w, -0.0076224613f);
        p = fmaf(p, w, 0.00943887047f);
        p = fmaf(p, w, 1.00167406f);
        p = fmaf(p, w, 2.83297682f);
    }
    return p * x;
}
__device__ __forceinline__ float jax_normal_from_bits(uint32_t bits) {
    float f = __uint_as_float((bits >> 9) | 0x3f800000u) - 1.0f;
    const float lo = -0.99999994f;
    float u = fmaxf(lo, fmaf(f, 2.0f, lo));
    return 1.41421356237f * jax_erfinv(u);
}
__device__ __forceinline__ float sigm(float v) { return 1.0f / (1.0f + expf(-v)); }

// ------------------------------- prep kernels ------------------------------
__global__ void prep_kernel(const float* __restrict__ B) {
    __shared__ float sS[66];
    int t = threadIdx.x;
    if (t < 66) {
        float rs = 0.0f;
        for (int k = 0; k < 66; k++) {
            if (k == t) continue;
            if (t == 65 && k < 64) continue;
            rs += sigm(B[t * 66 + k]);
        }
        sS[t] = 1.0f + rs / 66.0f;
    }
    if (t < 20) {
        uint32_t o0, o1;
        threefry2x32(0u, 42u, 0u, (uint32_t)t, o0, o1);
        g_sub[t] = make_uint2(o0, o1);
    }
    __syncthreads();
    if (t == 0) {
        float a64 = 0.0f;
        for (int j = 0; j < 66; j++)
            if (j != 64) a64 += sigm(B[64 * 66 + j]) * sS[j];
        float a65 = sigm(B[65 * 66 + 64]) * sS[64];
        g_q[0] = sS[64] + a64 / 66.0f;
        g_q[1] = sS[65] + a65 / 66.0f;
    }
}

__device__ __forceinline__ float wfold(const float* WT1, const float* WY1,
                                       float q0, float q1, int d, int kf) {
    return (kf < 128) ? q0 * WT1[d * 128 + kf] : q1 * WY1[d * 128 + kf - 128];
}

__global__ void prep2_kernel(const float* __restrict__ WT1, const float* __restrict__ WY1,
                             const float* __restrict__ bT1, const float* __restrict__ bY1,
                             const float* __restrict__ WT2, const float* __restrict__ WY2) {
    float q0 = g_q[0], q1 = g_q[1];
    int gt = blockIdx.x * blockDim.x + threadIdx.x;
    int gs = gridDim.x * blockDim.x;
    for (int i = gt; i < 32768; i += gs) {
        int reg = i & 1, lane = (i >> 1) & 31;
        { // Bf1: B[k=d][n=kf], pairs along d
            int nt = (i >> 6) & 31, kt = i >> 11;
            int d0 = (kt << 4) + ((lane & 3) << 1) + (reg << 3);
            int kf = (nt << 3) + (lane >> 2);
            gBf1[i] = cvt_bf16x2(wfold(WT1, WY1, q0, q1, d0 + 1, kf),
                                 wfold(WT1, WY1, q0, q1, d0, kf));
        }
        { // Bf2: B[k=kf][n=d], pairs along kf
            int nt = (i >> 6) & 15, kt = i >> 10;
            int kf0 = (kt << 4) + ((lane & 3) << 1) + (reg << 3);
            int d = (nt << 3) + (lane >> 2);
            gBf2[i] = cvt_bf16x2(wfold(WT1, WY1, q0, q1, d, kf0 + 1),
                                 wfold(WT1, WY1, q0, q1, d, kf0));
        }
    }
    if (gt < 256) {
        float b = (gt < 128) ? bT1[gt] : bY1[gt - 128];
        float v = (gt < 128) ? WT2[gt] : WY2[gt - 128];
        gBV[gt] = cvt_bf16x2(v, b);
    }
}

// ------------------------------- main kernel -------------------------------
__global__ void __launch_bounds__(NTH, 1)
main_kernel(const float* __restrict__ x, const float* __restrict__ tvec,
            const float* __restrict__ Win, const float* __restrict__ bin,
            float* __restrict__ out) {
    extern __shared__ unsigned char sraw[];
    const int tid = threadIdx.x;
    const int w = tid >> 5, lane = tid & 31;
    const int g = lane >> 2, t2 = (lane & 3) << 1;
    const int b0 = blockIdx.x * MPC;

    float2* WZp = (float2*)(sraw + OFF_WZ);
    float2* ZSp = (float2*)(sraw + OFF_ZS);

    // ---- stage: Bf2 copy; Xs -> AF2 region; WinS -> BF1 region ----
    for (int i = tid; i < 4096; i += NTH)
        ((uint4*)(sraw + OFF_BF2))[i] = ((const uint4*)gBf2)[i];
    float* Xs = (float*)(sraw + OFF_AF2);      // [128][65]
    float* WinS = (float*)(sraw + OFF_BF1);    // [64][130]
    for (int i = tid; i < 8192; i += NTH) {
        int m = i >> 6, e = i & 63;
        Xs[m * 65 + e] = x[(size_t)(b0 + m) * 64 + e];
    }
    for (int i = tid; i < 8192; i += NTH) {
        int e = i >> 7, d = i & 127;
        WinS[e * 130 + d] = Win[i];
    }
    if (tid < 128) {
        WZp[tid] = make_float2(Win[64 * 128 + tid], Win[65 * 128 + tid]);
        ZSp[tid] = make_float2(tvec[b0 + tid], 0.0f);
    }
    if (tid < 256) ((uint32_t*)(sraw + OFF_BV))[tid] = gBV[tid];
    __syncthreads();

    // ---- C[mrows][cols] in regs, A1-frag mapping: warp (mtA = w&7, kth = w>>3)
    const int mtA = w & 7, kth = w >> 3;
    const int r0 = (mtA << 4) + g, r1 = r0 + 8;
    float C[4][4][2];
    #pragma unroll
    for (int kt = 0; kt < 4; kt++) {
        int ktg = (kth << 2) + kt;
        #pragma unroll
        for (int ch = 0; ch < 2; ch++) {
            int cb = (ktg << 4) + t2 + (ch << 3);
            float bi0 = bin[cb], bi1 = bin[cb + 1];
            C[kt][2 * ch][0] = bi0;     C[kt][2 * ch][1] = bi1;
            C[kt][2 * ch + 1][0] = bi0; C[kt][2 * ch + 1][1] = bi1;
        }
    }
    for (int e = 0; e < 64; e++) {
        float x0 = Xs[r0 * 65 + e], x1 = Xs[r1 * 65 + e];
        #pragma unroll
        for (int kt = 0; kt < 4; kt++) {
            int ktg = (kth << 2) + kt;
            #pragma unroll
            for (int ch = 0; ch < 2; ch++) {
                int cb = (ktg << 4) + t2 + (ch << 3);
                float2 wv = *(const float2*)&WinS[e * 130 + cb];
                C[kt][2 * ch][0]     = fmaf(x0, wv.x, C[kt][2 * ch][0]);
                C[kt][2 * ch][1]     = fmaf(x0, wv.y, C[kt][2 * ch][1]);
                C[kt][2 * ch + 1][0] = fmaf(x1, wv.x, C[kt][2 * ch + 1][0]);
                C[kt][2 * ch + 1][1] = fmaf(x1, wv.y, C[kt][2 * ch + 1][1]);
            }
        }
    }
    __syncthreads();
    // overwrite WinS region with Bf1
    for (int i = tid; i < 4096; i += NTH)
        ((uint4*)(sraw + OFF_BF1))[i] = ((const uint4*)gBf1)[i];
    __syncthreads();

    const int mp = w & 3, q4 = w >> 2;   // GEMM roles: (mp, kq) / (mp, dq)

    for (int s = 0; s < NSTEPS; s++) {
        // ---- Phase A: h0 = C + z.Wz; R bf16 -> Af1 frags ----
        {
            float2 z0 = ZSp[r0], z1 = ZSp[r1];
            #pragma unroll
            for (int kt = 0; kt < 4; kt++) {
                int ktg = (kth << 2) + kt;
                uint32_t a[4];
                #pragma unroll
                for (int ch = 0; ch < 2; ch++) {
                    int cb = (ktg << 4) + t2 + (ch << 3);
                    float4 wq = *(const float4*)(sraw + OFF_WZ + cb * 8);
                    float h00 = C[kt][2*ch][0]   + z0.x * wq.x + z0.y * wq.y;
                    float h01 = C[kt][2*ch][1]   + z0.x * wq.z + z0.y * wq.w;
                    float h10 = C[kt][2*ch+1][0] + z1.x * wq.x + z1.y * wq.y;
                    float h11 = C[kt][2*ch+1][1] + z1.x * wq.z + z1.y * wq.w;
                    a[2*ch]   = cvt_bf16x2(fmaxf(h01, 0.f), fmaxf(h00, 0.f));
                    a[2*ch+1] = cvt_bf16x2(fmaxf(h11, 0.f), fmaxf(h10, 0.f));
                }
                *(uint4*)(sraw + af1_off(mtA, ktg, lane)) = make_uint4(a[0], a[1], a[2], a[3]);
            }
        }
        __syncthreads();

        // ---- GEMM1 + epilogue -> Af2 ----
        {
            uint32_t Ar[2][8][4];
            #pragma unroll
            for (int i = 0; i < 2; i++)
                #pragma unroll
                for (int kt = 0; kt < 8; kt++) {
                    uint4 v = *(const uint4*)(sraw + af1_off(2 * mp + i, kt, lane));
                    Ar[i][kt][0] = v.x; Ar[i][kt][1] = v.y; Ar[i][kt][2] = v.z; Ar[i][kt][3] = v.w;
                }
            uint32_t outb[2][4];
            #pragma unroll
            for (int nt = 0; nt < 8; nt++) {
                float c0[4] = {0.f, 0.f, 0.f, 0.f}, c1[4] = {0.f, 0.f, 0.f, 0.f};
                int ntg = (q4 << 3) + nt;
                #pragma unroll
                for (int kt = 0; kt < 8; kt++) {
                    uint2 b = *(const uint2*)(sraw + bf1_off(kt, ntg, lane));
                    MMA4(c0, Ar[0][kt], b.x, b.y);
                    MMA4(c1, Ar[1][kt], b.x, b.y);
                }
                int kf = (q4 << 6) + (nt << 3) + t2;
                uint32_t bv0 = *(const uint32_t*)(sraw + OFF_BV + kf * 4);
                uint32_t bv1 = *(const uint32_t*)(sraw + OFF_BV + kf * 4 + 4);
                float bb0 = bf16lo(bv0), vv0 = bf16hi(bv0);
                float bb1 = bf16lo(bv1), vv1 = bf16hi(bv1);
                int rs = (nt & 1) << 1;
                outb[0][rs]     = cvt_bf16x2((c0[1]+bb1) > 0.f ? vv1 : 0.f, (c0[0]+bb0) > 0.f ? vv0 : 0.f);
                outb[0][rs + 1] = cvt_bf16x2((c0[3]+bb1) > 0.f ? vv1 : 0.f, (c0[2]+bb0) > 0.f ? vv0 : 0.f);
                outb[1][rs]     = cvt_bf16x2((c1[1]+bb1) > 0.f ? vv1 : 0.f, (c1[0]+bb0) > 0.f ? vv0 : 0.f);
                outb[1][rs + 1] = cvt_bf16x2((c1[3]+bb1) > 0.f ? vv1 : 0.f, (c1[2]+bb0) > 0.f ? vv0 : 0.f);
                if (nt & 1) {
                    int ktA2 = (q4 << 2) + (nt >> 1);
                    *(uint4*)(sraw + af2_off(2 * mp,     ktA2, lane)) = make_uint4(outb[0][0], outb[0][1], outb[0][2], outb[0][3]);
                    *(uint4*)(sraw + af2_off(2 * mp + 1, ktA2, lane)) = make_uint4(outb[1][0], outb[1][1], outb[1][2], outb[1][3]);
                }
            }
        }
        __syncthreads();

        // ---- GEMM2 + phase-D partials ----
        float gx[4] = {0.f, 0.f, 0.f, 0.f}, gy[4] = {0.f, 0.f, 0.f, 0.f};
        {
            float acc[2][4][4];
            #pragma unroll
            for (int i = 0; i < 2; i++)
                #pragma unroll
                for (int nt = 0; nt < 4; nt++)
                    #pragma unroll
                    for (int r = 0; r < 4; r++) acc[i][nt][r] = 0.f;
            #pragma unroll
            for (int kt = 0; kt < 16; kt++) {
                uint4 va = *(const uint4*)(sraw + af2_off(2 * mp, kt, lane));
                uint4 vb = *(const uint4*)(sraw + af2_off(2 * mp + 1, kt, lane));
                uint32_t a0[4] = {va.x, va.y, va.z, va.w};
                uint32_t a1[4] = {vb.x, vb.y, vb.z, vb.w};
                #pragma unroll
                for (int nt = 0; nt < 4; nt++) {
                    uint2 b = *(const uint2*)(sraw + bf2_off(kt, (q4 << 2) + nt, lane));
                    MMA4(acc[0][nt], a0, b.x, b.y);
                    MMA4(acc[1][nt], a1, b.x, b.y);
                }
            }
            #pragma unroll
            for (int i = 0; i < 2; i++)
                #pragma unroll
                for (int nt = 0; nt < 4; nt++) {
                    int d0 = (q4 << 5) + (nt << 3) + t2;
                    int ktd = (q4 << 1) + (nt >> 1);
                    uint32_t mbase = af1_off(2 * mp + i, ktd, lane) + (uint32_t)((nt & 1) << 3);
                    uint32_t m0 = *(const uint32_t*)(sraw + mbase);
                    uint32_t m8 = *(const uint32_t*)(sraw + mbase + 4);
                    float4 wq = *(const float4*)(sraw + OFF_WZ + d0 * 8);
                    if (m0 & 0xFFFFu) { gx[2*i]   += wq.x * acc[i][nt][0]; gy[2*i]   += wq.y * acc[i][nt][0]; }
                    if (m0 >> 16)     { gx[2*i]   += wq.z * acc[i][nt][1]; gy[2*i]   += wq.w * acc[i][nt][1]; }
                    if (m8 & 0xFFFFu) { gx[2*i+1] += wq.x * acc[i][nt][2]; gy[2*i+1] += wq.y * acc[i][nt][2]; }
                    if (m8 >> 16)     { gx[2*i+1] += wq.z * acc[i][nt][3]; gy[2*i+1] += wq.w * acc[i][nt][3]; }
                }
            #pragma unroll
            for (int sl = 0; sl < 4; sl++) {
                gx[sl] += __shfl_xor_sync(0xffffffffu, gx[sl], 1);
                gx[sl] += __shfl_xor_sync(0xffffffffu, gx[sl], 2);
                gy[sl] += __shfl_xor_sync(0xffffffffu, gy[sl], 1);
                gy[sl] += __shfl_xor_sync(0xffffffffu, gy[sl], 2);
            }
        }
        __syncthreads();   // all mask reads of Af1 done -> safe to alias GP

        if ((lane & 3) == 0) {
            float2* GPp = (float2*)(sraw + OFF_AF1);
            #pragma unroll
            for (int sl = 0; sl < 4; sl++) {
                int row = (mp << 5) + ((sl >> 1) << 4) + g + ((sl & 1) << 3);
                GPp[(row << 2) + q4] = make_float2(gx[sl], gy[sl]);
            }
        }
        __syncthreads();

        if (tid < 128) {
            float4 gp01 = *(const float4*)(sraw + OFF_AF1 + tid * 32);
            float4 gp23 = *(const float4*)(sraw + OFF_AF1 + tid * 32 + 16);
            float gxs = (gp01.x + gp01.z) + (gp23.x + gp23.z);
            float gys = (gp01.y + gp01.w) + (gp23.y + gp23.w);
            uint2 sk = g_sub[s];
            uint32_t idx = ((uint32_t)(b0 + tid)) * 2u;
            uint32_t o0, o1;
            threefry2x32(sk.x, sk.y, 0u, idx, o0, o1);
            float n0 = jax_normal_from_bits(o0 ^ o1);
            threefry2x32(sk.x, sk.y, 0u, idx + 1u, o0, o1);
            float n1 = jax_normal_from_bits(o0 ^ o1);
            float2 z = ZSp[tid];
            z.x = z.x - 0.005f * gxs + 0.1f * n0;
            z.y = z.y - 0.005f * gys + 0.1f * n1;
            ZSp[tid] = z;
        }
        __syncthreads();
    }

    if (tid < 128) out[b0 + tid] = ZSp[tid].y;
}

// ---------------------------------------------------------------------------
extern "C" void kernel_launch(void* const* d_in, const int* in_sizes, int n_in,
                              void* d_out, int out_size) {
    (void)in_sizes; (void)n_in; (void)out_size;
    const float* x   = (const float*)d_in[0];
    const float* tv  = (const float*)d_in[1];
    const float* B   = (const float*)d_in[2];
    const float* Win = (const float*)d_in[3];
    const float* bin = (const float*)d_in[4];
    const float* WT1 = (const float*)d_in[5];
    const float* bT1 = (const float*)d_in[6];
    const float* WT2 = (const float*)d_in[7];
    const float* WY1 = (const float*)d_in[9];
    const float* bY1 = (const float*)d_in[10];
    const float* WY2 = (const float*)d_in[11];
    float* out = (float*)d_out;

    cudaFuncSetAttribute(main_kernel, cudaFuncAttributeMaxDynamicSharedMemorySize, SMEM_TOTAL);
    prep_kernel<<<1, 128>>>(B);
    prep2_kernel<<<64, 256>>>(WT1, WY1, bT1, bY1, WT2, WY2);
    main_kernel<<<NBLOCKS, NTH, SMEM_TOTAL>>>(x, tv, Win, bin, out);
}

// round 14
// speedup vs baseline: 4.5733x; 1.0240x over previous
#include <cuda_runtime.h>
#include <cuda_bf16.h>
#include <cstdint>

// ============================================================================
// GNN_EBM Langevin sampler — collapsed analytic form, HMMA (mma.sync bf16),
// single fused kernel (per-CTA q computation + weight-fragment folding).
// GEMM1: D1[m,kf] = R[m,d] @ Wf[d,kf]   (m16n8k16 frags, f32 acc)
// GEMM2: D2[m,d]  = Mmask[m,kf] @ Wf[d,kf]^T
// D1 frag -> A2 frag conversion happens in registers (same thread mapping).
// RNG: JAX partitionable threefry, bit-exact.
// R13 bug fixed: fold loop runs i<16384 (one valid Bf1 + Bf2 entry each);
// the old i<32768 bound made Bf1[i>=16384] clobber the whole Bf2 region.
// ============================================================================

#define NSTEPS  20
#define MPC     128
#define NTH     512
#define NBLOCKS (8192 / MPC)

#define OFF_BF1 0u          // B frags GEMM1: [kt8][nt32][lane32][2] u32 = 64KB
#define OFF_BF2 65536u      // B frags GEMM2: [kt16][nt16][lane32][2] u32 = 64KB
#define OFF_AF2 131072u     // A frags GEMM2: [mt8][kt16][lane32][4] u32 = 64KB
#define OFF_AF1 196608u     // A frags GEMM1: [mt8][kt8][lane32][4] u32 = 32KB
#define OFF_WZ  229376u     // float2 Wz[128] (1KB)
#define OFF_ZS  230400u     // float2 Z[128]  (1KB)
#define OFF_BV  231424u     // bf16x2 (bcat,vcat)[256] (1KB)
#define SMEM_TOTAL 232448   // = 227KB exactly

__device__ __forceinline__ uint32_t af1_off(int mt, int kt, int lane) {
    return OFF_AF1 + (uint32_t)((((mt << 3) + kt) << 9) + (lane << 4));
}
__device__ __forceinline__ uint32_t af2_off(int mt, int kt, int lane) {
    return OFF_AF2 + (uint32_t)((((mt << 4) + kt) << 9) + (lane << 4));
}
__device__ __forceinline__ uint32_t bf1_off(int kt, int nt, int lane) {
    return OFF_BF1 + (uint32_t)((((kt << 5) + nt) << 8) + (lane << 3));
}
__device__ __forceinline__ uint32_t bf2_off(int kt, int nt, int lane) {
    return OFF_BF2 + (uint32_t)((((kt << 4) + nt) << 8) + (lane << 3));
}

__device__ __forceinline__ uint32_t cvt_bf16x2(float hi, float lo) {
    uint32_t u;
    asm("cvt.rn.bf16x2.f32 %0, %1, %2;" : "=r"(u) : "f"(hi), "f"(lo));
    return u;
}
__device__ __forceinline__ float bf16lo(uint32_t w) { return __uint_as_float(w << 16); }
__device__ __forceinline__ float bf16hi(uint32_t w) { return __uint_as_float(w & 0xffff0000u); }

#define MMA4(c, a, b0, b1) asm volatile( \
    "mma.sync.aligned.m16n8k16.row.col.f32.bf16.bf16.f32 " \
    "{%0,%1,%2,%3},{%4,%5,%6,%7},{%8,%9},{%0,%1,%2,%3};" \
    : "+f"((c)[0]), "+f"((c)[1]), "+f"((c)[2]), "+f"((c)[3]) \
    : "r"((a)[0]), "r"((a)[1]), "r"((a)[2]), "r"((a)[3]), "r"(b0), "r"(b1))

// --------------------------- threefry / normal -----------------------------
__device__ __forceinline__ uint32_t rotl32(uint32_t v, int r) { return (v << r) | (v >> (32 - r)); }
__device__ __forceinline__ void threefry2x32(uint32_t k0, uint32_t k1, uint32_t x0, uint32_t x1,
                                             uint32_t& o0, uint32_t& o1) {
    uint32_t k2 = k0 ^ k1 ^ 0x1BD11BDAu;
    x0 += k0; x1 += k1;
#define TFR(r) { x0 += x1; x1 = rotl32(x1, (r)); x1 ^= x0; }
    TFR(13) TFR(15) TFR(26) TFR(6)  x0 += k1; x1 += k2 + 1u;
    TFR(17) TFR(29) TFR(16) TFR(24) x0 += k2; x1 += k0 + 2u;
    TFR(13) TFR(15) TFR(26) TFR(6)  x0 += k0; x1 += k1 + 3u;
    TFR(17) TFR(29) TFR(16) TFR(24) x0 += k1; x1 += k2 + 4u;
    TFR(13) TFR(15) TFR(26) TFR(6)  x0 += k2; x1 += k0 + 5u;
#undef TFR
    o0 = x0; o1 = x1;
}
__device__ __forceinline__ float jax_erfinv(float x) {
    float w = -log1pf(-x * x);
    float p;
    if (w < 5.0f) {
        w = w - 2.5f;
        p = 2.81022636e-08f;
        p = fmaf(p, w, 3.43273939e-07f);
        p = fmaf(p, w, -3.5233877e-06f);
        p = fmaf(p, w, -4.39150654e-06f);
        p = fmaf(p, w, 0.00021858087f);
        p = fmaf(p, w, -0.00125372503f);
        p = fmaf(p, w, -0.00417768164f);
        p = fmaf(p, w, 0.246640727f);
        p = fmaf(p, w, 1.50140941f);
    } else {
        w = sqrtf(w) - 3.0f;
        p = -0.000200214257f;
        p = fmaf(p, w, 0.000100950558f);
        p = fmaf(p, w, 0.00134934322f);
        p = fmaf(p, w, -0.00367342844f);
        p = fmaf(p, w, 0.00573950773f);
        p = fmaf(p, w, -0.0076224613f);
        p = fmaf(p, w, 0.00943887047f);
        p = fmaf(p, w, 1.00167406f);
        p = fmaf(p, w, 2.83297682f);
    }
    return p * x;
}
__device__ __forceinline__ float jax_normal_from_bits(uint32_t bits) {
    float f = __uint_as_float((bits >> 9) | 0x3f800000u) - 1.0f;
    const float lo = -0.99999994f;
    float u = fmaxf(lo, fmaf(f, 2.0f, lo));
    return 1.41421356237f * jax_erfinv(u);
}
__device__ __forceinline__ float sigmf(float v) { return 1.0f / (1.0f + expf(-v)); }

__device__ __forceinline__ float wfold(const float* WT1, const float* WY1,
                                       float q0, float q1, int d, int kf) {
    return (kf < 128) ? q0 * WT1[d * 128 + kf] : q1 * WY1[d * 128 + kf - 128];
}

// ------------------------------- main kernel -------------------------------
__global__ void __launch_bounds__(NTH, 1)
main_kernel(const float* __restrict__ x, const float* __restrict__ tvec,
            const float* __restrict__ B,
            const float* __restrict__ Win, const float* __restrict__ bin,
            const float* __restrict__ WT1, const float* __restrict__ bT1,
            const float* __restrict__ WT2,
            const float* __restrict__ WY1, const float* __restrict__ bY1,
            const float* __restrict__ WY2,
            float* __restrict__ out) {
    extern __shared__ unsigned char sraw[];
    const int tid = threadIdx.x;
    const int w = tid >> 5, lane = tid & 31;
    const int g = lane >> 2, t2 = (lane & 3) << 1;
    const int b0 = blockIdx.x * MPC;

    float2* WZp = (float2*)(sraw + OFF_WZ);
    float2* ZSp = (float2*)(sraw + OFF_ZS);
    // prologue scratch in AF1 region (unused until step loop)
    float* sSs = (float*)(sraw + OFF_AF1);          // s values [66]
    float* p64 = (float*)(sraw + OFF_AF1 + 512);    // products for q0 [66]
    float* qq  = (float*)(sraw + OFF_AF1 + 1024);   // q0, q1

    // ---- stage: Xs -> AF2 region; WinS -> BF1 region; small tables ----
    float* Xs = (float*)(sraw + OFF_AF2);      // [128][65]
    float* WinS = (float*)(sraw + OFF_BF1);    // [64][130]
    for (int i = tid; i < 8192; i += NTH) {
        int m = i >> 6, e = i & 63;
        Xs[m * 65 + e] = x[(size_t)(b0 + m) * 64 + e];
    }
    for (int i = tid; i < 8192; i += NTH) {
        int e = i >> 7, d = i & 127;
        WinS[e * 130 + d] = Win[i];
    }
    if (tid < 128) {
        WZp[tid] = make_float2(Win[64 * 128 + tid], Win[65 * 128 + tid]);
        ZSp[tid] = make_float2(tvec[b0 + tid], 0.0f);
    }
    if (tid < 256) {
        float bb = (tid < 128) ? bT1[tid] : bY1[tid - 128];
        float vv = (tid < 128) ? WT2[tid] : WY2[tid - 128];
        ((uint32_t*)(sraw + OFF_BV))[tid] = cvt_bf16x2(vv, bb);
    }
    // per-CTA q computation: row sums of sigmoid(A) with mask
    if (tid < 66) {
        float rs = 0.0f;
        for (int k = 0; k < 66; k++) {
            if (k == tid) continue;
            if (tid == 65 && k < 64) continue;
            rs += sigmf(B[tid * 66 + k]);
        }
        float sv = 1.0f + rs / 66.0f;
        sSs[tid] = sv;
        p64[tid] = (tid != 64) ? sigmf(B[64 * 66 + tid]) * sv : 0.0f;
    }
    __syncthreads();
    if (tid == 0) {
        float a64 = 0.0f;
        for (int j = 0; j < 66; j++) a64 += p64[j];
        qq[0] = sSs[64] + a64 / 66.0f;
        qq[1] = sSs[65] + sigmf(B[65 * 66 + 64]) * sSs[64] / 66.0f;
    }

    // ---- C[mrows][cols] in regs, A1-frag mapping: warp (mtA = w&7, kth = w>>3)
    const int mtA = w & 7, kth = w >> 3;
    const int r0 = (mtA << 4) + g, r1 = r0 + 8;
    float C[4][4][2];
    #pragma unroll
    for (int kt = 0; kt < 4; kt++) {
        int ktg = (kth << 2) + kt;
        #pragma unroll
        for (int ch = 0; ch < 2; ch++) {
            int cb = (ktg << 4) + t2 + (ch << 3);
            float bi0 = bin[cb], bi1 = bin[cb + 1];
            C[kt][2 * ch][0] = bi0;     C[kt][2 * ch][1] = bi1;
            C[kt][2 * ch + 1][0] = bi0; C[kt][2 * ch + 1][1] = bi1;
        }
    }
    for (int e = 0; e < 64; e++) {
        float x0 = Xs[r0 * 65 + e], x1 = Xs[r1 * 65 + e];
        #pragma unroll
        for (int kt = 0; kt < 4; kt++) {
            int ktg = (kth << 2) + kt;
            #pragma unroll
            for (int ch = 0; ch < 2; ch++) {
                int cb = (ktg << 4) + t2 + (ch << 3);
                float2 wv = *(const float2*)&WinS[e * 130 + cb];
                C[kt][2 * ch][0]     = fmaf(x0, wv.x, C[kt][2 * ch][0]);
                C[kt][2 * ch][1]     = fmaf(x0, wv.y, C[kt][2 * ch][1]);
                C[kt][2 * ch + 1][0] = fmaf(x1, wv.x, C[kt][2 * ch + 1][0]);
                C[kt][2 * ch + 1][1] = fmaf(x1, wv.y, C[kt][2 * ch + 1][1]);
            }
        }
    }
    __syncthreads();

    // ---- fold weights into B frags (overwrites WinS region) ----
    // NOTE: bound is 16384 — exactly the valid frag entries for EACH of
    // Bf1 (kt<8) and Bf2 (kt<16). i>=16384 would write past Bf1 into Bf2.
    {
        const float q0 = qq[0], q1 = qq[1];
        uint32_t* Bf1 = (uint32_t*)(sraw + OFF_BF1);
        uint32_t* Bf2 = (uint32_t*)(sraw + OFF_BF2);
        for (int i = tid; i < 16384; i += NTH) {
            int reg = i & 1, ln = (i >> 1) & 31;
            { // Bf1: B[k=d][n=kf], pairs along d   (kt = i>>11 in [0,8))
                int nt = (i >> 6) & 31, kt = i >> 11;
                int d0 = (kt << 4) + ((ln & 3) << 1) + (reg << 3);
                int kf = (nt << 3) + (ln >> 2);
                Bf1[i] = cvt_bf16x2(wfold(WT1, WY1, q0, q1, d0 + 1, kf),
                                    wfold(WT1, WY1, q0, q1, d0, kf));
            }
            { // Bf2: B[k=kf][n=d], pairs along kf  (kt = i>>10 in [0,16))
                int nt = (i >> 6) & 15, kt = i >> 10;
                int kf0 = (kt << 4) + ((ln & 3) << 1) + (reg << 3);
                int d = (nt << 3) + (ln >> 2);
                Bf2[i] = cvt_bf16x2(wfold(WT1, WY1, q0, q1, d, kf0 + 1),
                                    wfold(WT1, WY1, q0, q1, d, kf0));
            }
        }
    }
    __syncthreads();

    const int mp = w & 3, q4 = w >> 2;   // GEMM roles: (mp, kq) / (mp, dq)

    for (int s = 0; s < NSTEPS; s++) {
        // ---- Phase A: h0 = C + z.Wz; R bf16 -> Af1 frags ----
        {
            float2 z0 = ZSp[r0], z1 = ZSp[r1];
            #pragma unroll
            for (int kt = 0; kt < 4; kt++) {
                int ktg = (kth << 2) + kt;
                uint32_t a[4];
                #pragma unroll
                for (int ch = 0; ch < 2; ch++) {
                    int cb = (ktg << 4) + t2 + (ch << 3);
                    float4 wq = *(const float4*)(sraw + OFF_WZ + cb * 8);
                    float h00 = C[kt][2*ch][0]   + z0.x * wq.x + z0.y * wq.y;
                    float h01 = C[kt][2*ch][1]   + z0.x * wq.z + z0.y * wq.w;
                    float h10 = C[kt][2*ch+1][0] + z1.x * wq.x + z1.y * wq.y;
                    float h11 = C[kt][2*ch+1][1] + z1.x * wq.z + z1.y * wq.w;
                    a[2*ch]   = cvt_bf16x2(fmaxf(h01, 0.f), fmaxf(h00, 0.f));
                    a[2*ch+1] = cvt_bf16x2(fmaxf(h11, 0.f), fmaxf(h10, 0.f));
                }
                *(uint4*)(sraw + af1_off(mtA, ktg, lane)) = make_uint4(a[0], a[1], a[2], a[3]);
            }
        }
        __syncthreads();

        // ---- GEMM1 + epilogue -> Af2 ----
        {
            uint32_t Ar[2][8][4];
            #pragma unroll
            for (int i = 0; i < 2; i++)
                #pragma unroll
                for (int kt = 0; kt < 8; kt++) {
                    uint4 v = *(const uint4*)(sraw + af1_off(2 * mp + i, kt, lane));
                    Ar[i][kt][0] = v.x; Ar[i][kt][1] = v.y; Ar[i][kt][2] = v.z; Ar[i][kt][3] = v.w;
                }
            uint32_t outb[2][4];
            #pragma unroll
            for (int nt = 0; nt < 8; nt++) {
                float c0[4] = {0.f, 0.f, 0.f, 0.f}, c1[4] = {0.f, 0.f, 0.f, 0.f};
                int ntg = (q4 << 3) + nt;
                #pragma unroll
                for (int kt = 0; kt < 8; kt++) {
                    uint2 b = *(const uint2*)(sraw + bf1_off(kt, ntg, lane));
                    MMA4(c0, Ar[0][kt], b.x, b.y);
                    MMA4(c1, Ar[1][kt], b.x, b.y);
                }
                int kf = (q4 << 6) + (nt << 3) + t2;
                uint32_t bv0 = *(const uint32_t*)(sraw + OFF_BV + kf * 4);
                uint32_t bv1 = *(const uint32_t*)(sraw + OFF_BV + kf * 4 + 4);
                float bb0 = bf16lo(bv0), vv0 = bf16hi(bv0);
                float bb1 = bf16lo(bv1), vv1 = bf16hi(bv1);
                int rs = (nt & 1) << 1;
                outb[0][rs]     = cvt_bf16x2((c0[1]+bb1) > 0.f ? vv1 : 0.f, (c0[0]+bb0) > 0.f ? vv0 : 0.f);
                outb[0][rs + 1] = cvt_bf16x2((c0[3]+bb1) > 0.f ? vv1 : 0.f, (c0[2]+bb0) > 0.f ? vv0 : 0.f);
                outb[1][rs]     = cvt_bf16x2((c1[1]+bb1) > 0.f ? vv1 : 0.f, (c1[0]+bb0) > 0.f ? vv0 : 0.f);
                outb[1][rs + 1] = cvt_bf16x2((c1[3]+bb1) > 0.f ? vv1 : 0.f, (c1[2]+bb0) > 0.f ? vv0 : 0.f);
                if (nt & 1) {
                    int ktA2 = (q4 << 2) + (nt >> 1);
                    *(uint4*)(sraw + af2_off(2 * mp,     ktA2, lane)) = make_uint4(outb[0][0], outb[0][1], outb[0][2], outb[0][3]);
                    *(uint4*)(sraw + af2_off(2 * mp + 1, ktA2, lane)) = make_uint4(outb[1][0], outb[1][1], outb[1][2], outb[1][3]);
                }
            }
        }
        __syncthreads();

        // ---- GEMM2 + phase-D partials ----
        float gx[4] = {0.f, 0.f, 0.f, 0.f}, gy[4] = {0.f, 0.f, 0.f, 0.f};
        {
            float acc[2][4][4];
            #pragma unroll
            for (int i = 0; i < 2; i++)
                #pragma unroll
                for (int nt = 0; nt < 4; nt++)
                    #pragma unroll
                    for (int r = 0; r < 4; r++) acc[i][nt][r] = 0.f;
            #pragma unroll
            for (int kt = 0; kt < 16; kt++) {
                uint4 va = *(const uint4*)(sraw + af2_off(2 * mp, kt, lane));
                uint4 vb = *(const uint4*)(sraw + af2_off(2 * mp + 1, kt, lane));
                uint32_t a0[4] = {va.x, va.y, va.z, va.w};
                uint32_t a1[4] = {vb.x, vb.y, vb.z, vb.w};
                #pragma unroll
                for (int nt = 0; nt < 4; nt++) {
                    uint2 b = *(const uint2*)(sraw + bf2_off(kt, (q4 << 2) + nt, lane));
                    MMA4(acc[0][nt], a0, b.x, b.y);
                    MMA4(acc[1][nt], a1, b.x, b.y);
                }
            }
            #pragma unroll
            for (int i = 0; i < 2; i++)
                #pragma unroll
                for (int nt = 0; nt < 4; nt++) {
                    int d0 = (q4 << 5) + (nt << 3) + t2;
                    int ktd = (q4 << 1) + (nt >> 1);
                    uint32_t mbase = af1_off(2 * mp + i, ktd, lane) + (uint32_t)((nt & 1) << 3);
                    uint32_t m0 = *(const uint32_t*)(sraw + mbase);
                    uint32_t m8 = *(const uint32_t*)(sraw + mbase + 4);
                    float4 wq = *(const float4*)(sraw + OFF_WZ + d0 * 8);
                    if (m0 & 0xFFFFu) { gx[2*i]   += wq.x * acc[i][nt][0]; gy[2*i]   += wq.y * acc[i][nt][0]; }
                    if (m0 >> 16)     { gx[2*i]   += wq.z * acc[i][nt][1]; gy[2*i]   += wq.w * acc[i][nt][1]; }
                    if (m8 & 0xFFFFu) { gx[2*i+1] += wq.x * acc[i][nt][2]; gy[2*i+1] += wq.y * acc[i][nt][2]; }
                    if (m8 >> 16)     { gx[2*i+1] += wq.z * acc[i][nt][3]; gy[2*i+1] += wq.w * acc[i][nt][3]; }
                }
            #pragma unroll
            for (int sl = 0; sl < 4; sl++) {
                gx[sl] += __shfl_xor_sync(0xffffffffu, gx[sl], 1);
                gx[sl] += __shfl_xor_sync(0xffffffffu, gx[sl], 2);
                gy[sl] += __shfl_xor_sync(0xffffffffu, gy[sl], 1);
                gy[sl] += __shfl_xor_sync(0xffffffffu, gy[sl], 2);
            }
        }
        __syncthreads();   // all mask reads of Af1 done -> safe to alias GP

        if ((lane & 3) == 0) {
            float2* GPp = (float2*)(sraw + OFF_AF1);
            #pragma unroll
            for (int sl = 0; sl < 4; sl++) {
                int row = (mp << 5) + ((sl >> 1) << 4) + g + ((sl & 1) << 3);
                GPp[(row << 2) + q4] = make_float2(gx[sl], gy[sl]);
            }
        }
        __syncthreads();

        if (tid < 128) {
            float4 gp01 = *(const float4*)(sraw + OFF_AF1 + tid * 32);
            float4 gp23 = *(const float4*)(sraw + OFF_AF1 + tid * 32 + 16);
            float gxs = (gp01.x + gp01.z) + (gp23.x + gp23.z);
            float gys = (gp01.y + gp01.w) + (gp23.y + gp23.w);
            uint32_t sk0, sk1;
            threefry2x32(0u, 42u, 0u, (uint32_t)s, sk0, sk1);   // subkey s
            uint32_t idx = ((uint32_t)(b0 + tid)) * 2u;
            uint32_t o0, o1;
            threefry2x32(sk0, sk1, 0u, idx, o0, o1);
            float n0 = jax_normal_from_bits(o0 ^ o1);
            threefry2x32(sk0, sk1, 0u, idx + 1u, o0, o1);
            float n1 = jax_normal_from_bits(o0 ^ o1);
            float2 z = ZSp[tid];
            z.x = z.x - 0.005f * gxs + 0.1f * n0;
            z.y = z.y - 0.005f * gys + 0.1f * n1;
            ZSp[tid] = z;
        }
        __syncthreads();
    }

    if (tid < 128) out[b0 + tid] = ZSp[tid].y;
}

// ---------------------------------------------------------------------------
extern "C" void kernel_launch(void* const* d_in, const int* in_sizes, int n_in,
                              void* d_out, int out_size) {
    (void)in_sizes; (void)n_in; (void)out_size;
    const float* x   = (const float*)d_in[0];
    const float* tv  = (const float*)d_in[1];
    const float* B   = (const float*)d_in[2];
    const float* Win = (const float*)d_in[3];
    const float* bin = (const float*)d_in[4];
    const float* WT1 = (const float*)d_in[5];
    const float* bT1 = (const float*)d_in[6];
    const float* WT2 = (const float*)d_in[7];
    const float* WY1 = (const float*)d_in[9];
    const float* bY1 = (const float*)d_in[10];
    const float* WY2 = (const float*)d_in[11];
    float* out = (float*)d_out;

    cudaFuncSetAttribute(main_kernel, cudaFuncAttributeMaxDynamicSharedMemorySize, SMEM_TOTAL);
    main_kernel<<<NBLOCKS, NTH, SMEM_TOTAL>>>(x, tv, B, Win, bin, WT1, bT1, WT2,
                                              WY1, bY1, WY2, out);
}

// round 15
// speedup vs baseline: 6.3398x; 1.3863x over previous
#include <cuda_runtime.h>
#include <cuda_bf16.h>
#include <cstdint>

// ============================================================================
// GNN_EBM Langevin sampler — collapsed analytic form, HMMA (mma.sync bf16),
// single fused kernel. R14: MPC=64, grid=128 -> 128/148 SMs busy (was 64).
// GEMM1: D1[m,kf] = R[m,d] @ Wf[d,kf]   (m16n8k16 frags, f32 acc)
// GEMM2: D2[m,d]  = Mmask[m,kf] @ Wf[d,kf]^T
// D1 frag -> A2 frag conversion in registers (same thread mapping).
// RNG: JAX partitionable threefry, bit-exact.
// ============================================================================

#define NSTEPS  20
#define MPC     64
#define NTH     512
#define NBLOCKS (8192 / MPC)    // 128

#define OFF_BF1 0u          // B frags GEMM1: [kt8][nt32][lane32][2] u32 = 64KB
#define OFF_BF2 65536u      // B frags GEMM2: [kt16][nt16][lane32][2] u32 = 64KB
#define OFF_AF2 131072u     // A frags GEMM2: [mt4][kt16][lane32][4] u32 = 32KB
#define OFF_AF1 163840u     // A frags GEMM1: [mt4][kt8][lane32][4] u32 = 16KB
#define OFF_WZ  180224u     // float2 Wz[128] (1KB)
#define OFF_ZS  181248u     // float2 Z[64]   (512B)
#define OFF_BV  181760u     // bf16x2 (bcat,vcat)[256] (1KB)
#define SMEM_TOTAL 182784

__device__ __forceinline__ uint32_t af1_off(int mt, int kt, int lane) {
    return OFF_AF1 + (uint32_t)((((mt << 3) + kt) << 9) + (lane << 4));
}
__device__ __forceinline__ uint32_t af2_off(int mt, int kt, int lane) {
    return OFF_AF2 + (uint32_t)((((mt << 4) + kt) << 9) + (lane << 4));
}
__device__ __forceinline__ uint32_t bf1_off(int kt, int nt, int lane) {
    return OFF_BF1 + (uint32_t)((((kt << 5) + nt) << 8) + (lane << 3));
}
__device__ __forceinline__ uint32_t bf2_off(int kt, int nt, int lane) {
    return OFF_BF2 + (uint32_t)((((kt << 4) + nt) << 8) + (lane << 3));
}

__device__ __forceinline__ uint32_t cvt_bf16x2(float hi, float lo) {
    uint32_t u;
    asm("cvt.rn.bf16x2.f32 %0, %1, %2;" : "=r"(u) : "f"(hi), "f"(lo));
    return u;
}
__device__ __forceinline__ float bf16lo(uint32_t w) { return __uint_as_float(w << 16); }
__device__ __forceinline__ float bf16hi(uint32_t w) { return __uint_as_float(w & 0xffff0000u); }

#define MMA4(c, a, b0, b1) asm volatile( \
    "mma.sync.aligned.m16n8k16.row.col.f32.bf16.bf16.f32 " \
    "{%0,%1,%2,%3},{%4,%5,%6,%7},{%8,%9},{%0,%1,%2,%3};" \
    : "+f"((c)[0]), "+f"((c)[1]), "+f"((c)[2]), "+f"((c)[3]) \
    : "r"((a)[0]), "r"((a)[1]), "r"((a)[2]), "r"((a)[3]), "r"(b0), "r"(b1))

// --------------------------- threefry / normal -----------------------------
__device__ __forceinline__ uint32_t rotl32(uint32_t v, int r) { return (v << r) | (v >> (32 - r)); }
__device__ __forceinline__ void threefry2x32(uint32_t k0, uint32_t k1, uint32_t x0, uint32_t x1,
                                             uint32_t& o0, uint32_t& o1) {
    uint32_t k2 = k0 ^ k1 ^ 0x1BD11BDAu;
    x0 += k0; x1 += k1;
#define TFR(r) { x0 += x1; x1 = rotl32(x1, (r)); x1 ^= x0; }
    TFR(13) TFR(15) TFR(26) TFR(6)  x0 += k1; x1 += k2 + 1u;
    TFR(17) TFR(29) TFR(16) TFR(24) x0 += k2; x1 += k0 + 2u;
    TFR(13) TFR(15) TFR(26) TFR(6)  x0 += k0; x1 += k1 + 3u;
    TFR(17) TFR(29) TFR(16) TFR(24) x0 += k1; x1 += k2 + 4u;
    TFR(13) TFR(15) TFR(26) TFR(6)  x0 += k2; x1 += k0 + 5u;
#undef TFR
    o0 = x0; o1 = x1;
}
__device__ __forceinline__ float jax_erfinv(float x) {
    float w = -log1pf(-x * x);
    float p;
    if (w < 5.0f) {
        w = w - 2.5f;
        p = 2.81022636e-08f;
        p = fmaf(p, w, 3.43273939e-07f);
        p = fmaf(p, w, -3.5233877e-06f);
        p = fmaf(p, w, -4.39150654e-06f);
        p = fmaf(p, w, 0.00021858087f);
        p = fmaf(p, w, -0.00125372503f);
        p = fmaf(p, w, -0.00417768164f);
        p = fmaf(p, w, 0.246640727f);
        p = fmaf(p, w, 1.50140941f);
    } else {
        w = sqrtf(w) - 3.0f;
        p = -0.000200214257f;
        p = fmaf(p, w, 0.000100950558f);
        p = fmaf(p, w, 0.00134934322f);
        p = fmaf(p, w, -0.00367342844f);
        p = fmaf(p, w, 0.00573950773f);
        p = fmaf(p, w, -0.0076224613f);
        p = fmaf(p, w, 0.00943887047f);
        p = fmaf(p, w, 1.00167406f);
        p = fmaf(p, w, 2.83297682f);
    }
    return p * x;
}
__device__ __forceinline__ float jax_normal_from_bits(uint32_t bits) {
    float f = __uint_as_float((bits >> 9) | 0x3f800000u) - 1.0f;
    const float lo = -0.99999994f;
    float u = fmaxf(lo, fmaf(f, 2.0f, lo));
    return 1.41421356237f * jax_erfinv(u);
}
__device__ __forceinline__ float sigmf(float v) { return 1.0f / (1.0f + expf(-v)); }

__device__ __forceinline__ float wfold(const float* WT1, const float* WY1,
                                       float q0, float q1, int d, int kf) {
    return (kf < 128) ? q0 * WT1[d * 128 + kf] : q1 * WY1[d * 128 + kf - 128];
}

// ------------------------------- main kernel -------------------------------
__global__ void __launch_bounds__(NTH, 1)
main_kernel(const float* __restrict__ x, const float* __restrict__ tvec,
            const float* __restrict__ B,
            const float* __restrict__ Win, const float* __restrict__ bin,
            const float* __restrict__ WT1, const float* __restrict__ bT1,
            const float* __restrict__ WT2,
            const float* __restrict__ WY1, const float* __restrict__ bY1,
            const float* __restrict__ WY2,
            float* __restrict__ out) {
    extern __shared__ unsigned char sraw[];
    const int tid = threadIdx.x;
    const int w = tid >> 5, lane = tid & 31;
    const int g = lane >> 2, t2 = (lane & 3) << 1;
    const int b0 = blockIdx.x * MPC;

    float2* WZp = (float2*)(sraw + OFF_WZ);
    float2* ZSp = (float2*)(sraw + OFF_ZS);
    // prologue scratch in AF1 region
    float* sSs = (float*)(sraw + OFF_AF1);
    float* p64 = (float*)(sraw + OFF_AF1 + 512);
    float* qq  = (float*)(sraw + OFF_AF1 + 1024);

    // ---- stage: Xs -> AF2 region; WinS -> BF1 region; small tables ----
    float* Xs = (float*)(sraw + OFF_AF2);      // [64][65]
    float* WinS = (float*)(sraw + OFF_BF1);    // [64][130]
    for (int i = tid; i < MPC * 64; i += NTH) {
        int m = i >> 6, e = i & 63;
        Xs[m * 65 + e] = x[(size_t)(b0 + m) * 64 + e];
    }
    for (int i = tid; i < 8192; i += NTH) {
        int e = i >> 7, d = i & 127;
        WinS[e * 130 + d] = Win[i];
    }
    if (tid < 128) WZp[tid] = make_float2(Win[64 * 128 + tid], Win[65 * 128 + tid]);
    if (tid < MPC) ZSp[tid] = make_float2(tvec[b0 + tid], 0.0f);
    if (tid < 256) {
        float bb = (tid < 128) ? bT1[tid] : bY1[tid - 128];
        float vv = (tid < 128) ? WT2[tid] : WY2[tid - 128];
        ((uint32_t*)(sraw + OFF_BV))[tid] = cvt_bf16x2(vv, bb);
    }
    // per-CTA q computation
    if (tid < 66) {
        float rs = 0.0f;
        for (int k = 0; k < 66; k++) {
            if (k == tid) continue;
            if (tid == 65 && k < 64) continue;
            rs += sigmf(B[tid * 66 + k]);
        }
        float sv = 1.0f + rs / 66.0f;
        sSs[tid] = sv;
        p64[tid] = (tid != 64) ? sigmf(B[64 * 66 + tid]) * sv : 0.0f;
    }
    __syncthreads();
    if (tid == 0) {
        float a64 = 0.0f;
        for (int j = 0; j < 66; j++) a64 += p64[j];
        qq[0] = sSs[64] + a64 / 66.0f;
        qq[1] = sSs[65] + sigmf(B[65 * 66 + 64]) * sSs[64] / 66.0f;
    }

    // ---- C in regs; A1-frag mapping: warp (mtA = w&3, kth = w>>2) ----
    const int mtA = w & 3, kth = w >> 2;       // mtA<4, kth<4 (2 kt each)
    const int r0 = (mtA << 4) + g, r1 = r0 + 8;
    float C[2][4][2];
    #pragma unroll
    for (int kt = 0; kt < 2; kt++) {
        int ktg = (kth << 1) + kt;
        #pragma unroll
        for (int ch = 0; ch < 2; ch++) {
            int cb = (ktg << 4) + t2 + (ch << 3);
            float bi0 = bin[cb], bi1 = bin[cb + 1];
            C[kt][2 * ch][0] = bi0;     C[kt][2 * ch][1] = bi1;
            C[kt][2 * ch + 1][0] = bi0; C[kt][2 * ch + 1][1] = bi1;
        }
    }
    for (int e = 0; e < 64; e++) {
        float x0 = Xs[r0 * 65 + e], x1 = Xs[r1 * 65 + e];
        #pragma unroll
        for (int kt = 0; kt < 2; kt++) {
            int ktg = (kth << 1) + kt;
            #pragma unroll
            for (int ch = 0; ch < 2; ch++) {
                int cb = (ktg << 4) + t2 + (ch << 3);
                float2 wv = *(const float2*)&WinS[e * 130 + cb];
                C[kt][2 * ch][0]     = fmaf(x0, wv.x, C[kt][2 * ch][0]);
                C[kt][2 * ch][1]     = fmaf(x0, wv.y, C[kt][2 * ch][1]);
                C[kt][2 * ch + 1][0] = fmaf(x1, wv.x, C[kt][2 * ch + 1][0]);
                C[kt][2 * ch + 1][1] = fmaf(x1, wv.y, C[kt][2 * ch + 1][1]);
            }
        }
    }
    __syncthreads();

    // ---- fold weights into B frags (i<16384: one valid Bf1+Bf2 entry each) --
    {
        const float q0 = qq[0], q1 = qq[1];
        uint32_t* Bf1 = (uint32_t*)(sraw + OFF_BF1);
        uint32_t* Bf2 = (uint32_t*)(sraw + OFF_BF2);
        for (int i = tid; i < 16384; i += NTH) {
            int reg = i & 1, ln = (i >> 1) & 31;
            {
                int nt = (i >> 6) & 31, kt = i >> 11;
                int d0 = (kt << 4) + ((ln & 3) << 1) + (reg << 3);
                int kf = (nt << 3) + (ln >> 2);
                Bf1[i] = cvt_bf16x2(wfold(WT1, WY1, q0, q1, d0 + 1, kf),
                                    wfold(WT1, WY1, q0, q1, d0, kf));
            }
            {
                int nt = (i >> 6) & 15, kt = i >> 10;
                int kf0 = (kt << 4) + ((ln & 3) << 1) + (reg << 3);
                int d = (nt << 3) + (ln >> 2);
                Bf2[i] = cvt_bf16x2(wfold(WT1, WY1, q0, q1, d, kf0 + 1),
                                    wfold(WT1, WY1, q0, q1, d, kf0));
            }
        }
    }
    __syncthreads();

    const int mp = w & 1, q8 = w >> 1;   // GEMM roles

    for (int s = 0; s < NSTEPS; s++) {
        // ---- Phase A: h0 = C + z.Wz; R bf16 -> Af1 frags ----
        {
            float2 z0 = ZSp[r0], z1 = ZSp[r1];
            #pragma unroll
            for (int kt = 0; kt < 2; kt++) {
                int ktg = (kth << 1) + kt;
                uint32_t a[4];
                #pragma unroll
                for (int ch = 0; ch < 2; ch++) {
                    int cb = (ktg << 4) + t2 + (ch << 3);
                    float4 wq = *(const float4*)(sraw + OFF_WZ + cb * 8);
                    float h00 = C[kt][2*ch][0]   + z0.x * wq.x + z0.y * wq.y;
                    float h01 = C[kt][2*ch][1]   + z0.x * wq.z + z0.y * wq.w;
                    float h10 = C[kt][2*ch+1][0] + z1.x * wq.x + z1.y * wq.y;
                    float h11 = C[kt][2*ch+1][1] + z1.x * wq.z + z1.y * wq.w;
                    a[2*ch]   = cvt_bf16x2(fmaxf(h01, 0.f), fmaxf(h00, 0.f));
                    a[2*ch+1] = cvt_bf16x2(fmaxf(h11, 0.f), fmaxf(h10, 0.f));
                }
                *(uint4*)(sraw + af1_off(mtA, ktg, lane)) = make_uint4(a[0], a[1], a[2], a[3]);
            }
        }
        __syncthreads();

        // ---- GEMM1 + epilogue -> Af2 ----
        {
            uint32_t Ar[2][8][4];
            #pragma unroll
            for (int i = 0; i < 2; i++)
                #pragma unroll
                for (int kt = 0; kt < 8; kt++) {
                    uint4 v = *(const uint4*)(sraw + af1_off(2 * mp + i, kt, lane));
                    Ar[i][kt][0] = v.x; Ar[i][kt][1] = v.y; Ar[i][kt][2] = v.z; Ar[i][kt][3] = v.w;
                }
            uint32_t outb[2][4];
            #pragma unroll
            for (int nt = 0; nt < 4; nt++) {
                float c0[4] = {0.f, 0.f, 0.f, 0.f}, c1[4] = {0.f, 0.f, 0.f, 0.f};
                int ntg = (q8 << 2) + nt;
                #pragma unroll
                for (int kt = 0; kt < 8; kt++) {
                    uint2 b = *(const uint2*)(sraw + bf1_off(kt, ntg, lane));
                    MMA4(c0, Ar[0][kt], b.x, b.y);
                    MMA4(c1, Ar[1][kt], b.x, b.y);
                }
                int kf = (ntg << 3) + t2;
                uint32_t bv0 = *(const uint32_t*)(sraw + OFF_BV + kf * 4);
                uint32_t bv1 = *(const uint32_t*)(sraw + OFF_BV + kf * 4 + 4);
                float bb0 = bf16lo(bv0), vv0 = bf16hi(bv0);
                float bb1 = bf16lo(bv1), vv1 = bf16hi(bv1);
                int rs = (nt & 1) << 1;
                outb[0][rs]     = cvt_bf16x2((c0[1]+bb1) > 0.f ? vv1 : 0.f, (c0[0]+bb0) > 0.f ? vv0 : 0.f);
                outb[0][rs + 1] = cvt_bf16x2((c0[3]+bb1) > 0.f ? vv1 : 0.f, (c0[2]+bb0) > 0.f ? vv0 : 0.f);
                outb[1][rs]     = cvt_bf16x2((c1[1]+bb1) > 0.f ? vv1 : 0.f, (c1[0]+bb0) > 0.f ? vv0 : 0.f);
                outb[1][rs + 1] = cvt_bf16x2((c1[3]+bb1) > 0.f ? vv1 : 0.f, (c1[2]+bb0) > 0.f ? vv0 : 0.f);
                if (nt & 1) {
                    int ktA2 = (q8 << 1) + (nt >> 1);
                    *(uint4*)(sraw + af2_off(2 * mp,     ktA2, lane)) = make_uint4(outb[0][0], outb[0][1], outb[0][2], outb[0][3]);
                    *(uint4*)(sraw + af2_off(2 * mp + 1, ktA2, lane)) = make_uint4(outb[1][0], outb[1][1], outb[1][2], outb[1][3]);
                }
            }
        }
        __syncthreads();

        // ---- GEMM2 + phase-D partials ----
        float gx[4] = {0.f, 0.f, 0.f, 0.f}, gy[4] = {0.f, 0.f, 0.f, 0.f};
        {
            float acc[2][2][4];
            #pragma unroll
            for (int i = 0; i < 2; i++)
                #pragma unroll
                for (int nt = 0; nt < 2; nt++)
                    #pragma unroll
                    for (int r = 0; r < 4; r++) acc[i][nt][r] = 0.f;
            #pragma unroll
            for (int kt = 0; kt < 16; kt++) {
                uint4 va = *(const uint4*)(sraw + af2_off(2 * mp, kt, lane));
                uint4 vb = *(const uint4*)(sraw + af2_off(2 * mp + 1, kt, lane));
                uint32_t a0[4] = {va.x, va.y, va.z, va.w};
                uint32_t a1[4] = {vb.x, vb.y, vb.z, vb.w};
                #pragma unroll
                for (int nt = 0; nt < 2; nt++) {
                    uint2 b = *(const uint2*)(sraw + bf2_off(kt, (q8 << 1) + nt, lane));
                    MMA4(acc[0][nt], a0, b.x, b.y);
                    MMA4(acc[1][nt], a1, b.x, b.y);
                }
            }
            #pragma unroll
            for (int i = 0; i < 2; i++)
                #pragma unroll
                for (int nt = 0; nt < 2; nt++) {
                    int ntg = (q8 << 1) + nt;
                    int d0 = (ntg << 3) + t2;
                    uint32_t mbase = af1_off(2 * mp + i, q8, lane) + (uint32_t)(nt << 3);
                    uint32_t m0 = *(const uint32_t*)(sraw + mbase);
                    uint32_t m8 = *(const uint32_t*)(sraw + mbase + 4);
                    float4 wq = *(const float4*)(sraw + OFF_WZ + d0 * 8);
                    if (m0 & 0xFFFFu) { gx[2*i]   += wq.x * acc[i][nt][0]; gy[2*i]   += wq.y * acc[i][nt][0]; }
                    if (m0 >> 16)     { gx[2*i]   += wq.z * acc[i][nt][1]; gy[2*i]   += wq.w * acc[i][nt][1]; }
                    if (m8 & 0xFFFFu) { gx[2*i+1] += wq.x * acc[i][nt][2]; gy[2*i+1] += wq.y * acc[i][nt][2]; }
                    if (m8 >> 16)     { gx[2*i+1] += wq.z * acc[i][nt][3]; gy[2*i+1] += wq.w * acc[i][nt][3]; }
                }
            #pragma unroll
            for (int sl = 0; sl < 4; sl++) {
                gx[sl] += __shfl_xor_sync(0xffffffffu, gx[sl], 1);
                gx[sl] += __shfl_xor_sync(0xffffffffu, gx[sl], 2);
                gy[sl] += __shfl_xor_sync(0xffffffffu, gy[sl], 1);
                gy[sl] += __shfl_xor_sync(0xffffffffu, gy[sl], 2);
            }
        }
        __syncthreads();   // mask reads of Af1 done -> safe to alias GP

        if ((lane & 3) == 0) {
            float2* GPp = (float2*)(sraw + OFF_AF1);   // [64 rows][8 q8-groups]
            #pragma unroll
            for (int sl = 0; sl < 4; sl++) {
                int row = (mp << 5) + ((sl >> 1) << 4) + g + ((sl & 1) << 3);
                GPp[(row << 3) + q8] = make_float2(gx[sl], gy[sl]);
            }
        }
        __syncthreads();

        if (tid < MPC) {
            const float4* gp = (const float4*)(sraw + OFF_AF1 + tid * 64);
            float gxs = 0.f, gys = 0.f;
            #pragma unroll
            for (int j = 0; j < 4; j++) {
                float4 v = gp[j];
                gxs += v.x + v.z;
                gys += v.y + v.w;
            }
            uint32_t sk0, sk1;
            threefry2x32(0u, 42u, 0u, (uint32_t)s, sk0, sk1);
            uint32_t idx = ((uint32_t)(b0 + tid)) * 2u;
            uint32_t o0, o1;
            threefry2x32(sk0, sk1, 0u, idx, o0, o1);
            float n0 = jax_normal_from_bits(o0 ^ o1);
            threefry2x32(sk0, sk1, 0u, idx + 1u, o0, o1);
            float n1 = jax_normal_from_bits(o0 ^ o1);
            float2 z = ZSp[tid];
            z.x = z.x - 0.005f * gxs + 0.1f * n0;
            z.y = z.y - 0.005f * gys + 0.1f * n1;
            ZSp[tid] = z;
        }
        __syncthreads();
    }

    if (tid < MPC) out[b0 + tid] = ZSp[tid].y;
}

// ---------------------------------------------------------------------------
extern "C" void kernel_launch(void* const* d_in, const int* in_sizes, int n_in,
                              void* d_out, int out_size) {
    (void)in_sizes; (void)n_in; (void)out_size;
    const float* x   = (const float*)d_in[0];
    const float* tv  = (const float*)d_in[1];
    const float* B   = (const float*)d_in[2];
    const float* Win = (const float*)d_in[3];
    const float* bin = (const float*)d_in[4];
    const float* WT1 = (const float*)d_in[5];
    const float* bT1 = (const float*)d_in[6];
    const float* WT2 = (const float*)d_in[7];
    const float* WY1 = (const float*)d_in[9];
    const float* bY1 = (const float*)d_in[10];
    const float* WY2 = (const float*)d_in[11];
    float* out = (float*)d_out;

    cudaFuncSetAttribute(main_kernel, cudaFuncAttributeMaxDynamicSharedMemorySize, SMEM_TOTAL);
    main_kernel<<<NBLOCKS, NTH, SMEM_TOTAL>>>(x, tv, B, Win, bin, WT1, bT1, WT2,
                                              WY1, bY1, WY2, out);
}